// round 6
// baseline (speedup 1.0000x reference)
#include <cuda_runtime.h>

#define BB 8
#define NN 2000
#define CC 81
#define NPAD 2048
#define MAXI 100
#define HH 512
#define WW 512
#define MSEL 256
#define GRID 132

// scratch (device globals: no allocation allowed)
__device__ float4 g_box4[BB * NN];
__device__ int g_cls[BB * NN];
__device__ unsigned long long g_key[BB * NPAD];
__device__ unsigned g_bar[2];  // monotone barrier counters (persist across replays)

struct P2 {
    unsigned long long s[NPAD];                                   // 16KB
    float sy1[MSEL], sx1[MSEL], sy2[MSEL], sx2[MSEL], ssc[MSEL];  // 5KB
    int scl[MSEL];                                                // 1KB
    unsigned Mm[MSEL * 8];                                        // 8KB
    float ky1[MAXI], kx1[MAXI], ky2[MAXI], kx2[MAXI], kar[MAXI];  // 2KB
    int s_kc, s_fb;
};
struct P3 {
    float ax1[8][MAXI], ax2[8][MAXI];
    int nact[8];
};

__device__ __forceinline__ void cswap(unsigned long long& v, int i, int j, int k) {
    unsigned long long pv = __shfl_xor_sync(0xffffffffu, v, j);
    bool take_max = (((i & k) == 0) ^ ((i & j) != 0));
    bool pick = take_max ? (pv > v) : (pv < v);
    if (pick) v = pv;
}

// monotone grid barrier: correct across arbitrarily many sequential launches
__device__ __forceinline__ void grid_bar(int i) {
    __threadfence();
    __syncthreads();
    if (threadIdx.x == 0) {
        unsigned t = atomicAdd(&g_bar[i], 1u);
        unsigned target = (t / GRID + 1u) * GRID;
        while (*(volatile unsigned*)&g_bar[i] < target) {}
    }
    __syncthreads();
}

__global__ void __launch_bounds__(1024, 1)
fused_all(const float* __restrict__ rois,
          const float* __restrict__ probs,
          const float* __restrict__ deltas,
          const float* __restrict__ stdv,
          float* __restrict__ det,
          float* __restrict__ mask) {
    __shared__ __align__(16) char smem_raw[sizeof(P2)];
    int tid = threadIdx.x;
    int lane = tid & 31;
    int wrp = tid >> 5;
    int bid = blockIdx.x;

    // ===================== Phase 1: refine (all blocks) =====================
    {
        int w = bid * 32 + wrp;  // warp task id; 4000 tasks of 4 proposals
        if (w < 4000) {
            int gw4 = w * 4;
            float best[4];
            int bc[4];
#pragma unroll
            for (int q = 0; q < 4; ++q) {
                const float* p = probs + (long long)(gw4 + q) * CC;
                float b0 = p[lane];
                float b1 = p[lane + 32];
                float b2 = (lane + 64 < CC) ? p[lane + 64] : -1.0f;
                int c = lane;
                float bst = b0;
                if (b1 > bst) { bst = b1; c = lane + 32; }
                if (b2 > bst) { bst = b2; c = lane + 64; }
                best[q] = bst;
                bc[q] = c;
            }
#pragma unroll
            for (int q = 0; q < 4; ++q) {
#pragma unroll
                for (int o = 16; o; o >>= 1) {
                    float ov = __shfl_down_sync(0xffffffffu, best[q], o);
                    int oc = __shfl_down_sync(0xffffffffu, bc[q], o);
                    if (ov > best[q] || (ov == best[q] && oc < bc[q])) { best[q] = ov; bc[q] = oc; }
                }
                best[q] = __shfl_sync(0xffffffffu, best[q], 0);
                bc[q] = __shfl_sync(0xffffffffu, bc[q], 0);
            }
            if (lane < 4) {
                int gw = gw4 + lane;
                float bst = best[lane];
                int c = bc[lane];
                float4 dd = *(const float4*)(deltas + ((long long)gw * CC + c) * 4);
                float dy = dd.x * stdv[0];
                float dx = dd.y * stdv[1];
                float dh = dd.z * stdv[2];
                float dw = dd.w * stdv[3];
                float4 rr = *(const float4*)(rois + gw * 4);
                float y1 = rr.x, x1 = rr.y, y2 = rr.z, x2 = rr.w;
                float h = y2 - y1, w2 = x2 - x1;
                float cy = y1 + 0.5f * h + dy * h;
                float cx = x1 + 0.5f * w2 + dx * w2;
                h = h * expf(dh);
                w2 = w2 * expf(dw);
                float4 nb;
                nb.x = fminf(fmaxf(cy - 0.5f * h, 0.0f), 1.0f);
                nb.y = fminf(fmaxf(cx - 0.5f * w2, 0.0f), 1.0f);
                nb.z = fminf(fmaxf(cy + 0.5f * h, 0.0f), 1.0f);
                nb.w = fminf(fmaxf(cx + 0.5f * w2, 0.0f), 1.0f);
                g_box4[gw] = nb;
                g_cls[gw] = c;
                int b = gw / NN;
                int n = gw - b * NN;
                bool valid = (c > 0) && (bst >= 0.05f);
                unsigned long long key =
                    valid ? ((((unsigned long long)__float_as_uint(bst)) << 32) |
                             (unsigned long long)(0xFFFFFFFFu - (unsigned)n))
                          : 0ull;
                g_key[b * NPAD + n] = key;
            }
        }
    }
    grid_bar(0);

    // ===================== Phase 2: sort + NMS (blocks 0..7) =====================
    if (bid < BB) {
        P2& P = *(P2*)smem_raw;
        int b = bid;
        int t2 = tid + 1024;

        P.s[tid] = (tid < NN) ? g_key[b * NPAD + tid] : 0ull;
        P.s[t2] = (t2 < NN) ? g_key[b * NPAD + t2] : 0ull;
        __syncthreads();

        int i0 = wrp * 64 + lane;
        int i1 = wrp * 64 + 32 + lane;
        {   // stages k=2..64 in registers
            unsigned long long r0 = P.s[i0], r1 = P.s[i1];
#pragma unroll
            for (int k = 2; k <= 32; k <<= 1)
#pragma unroll
                for (int j = k >> 1; j > 0; j >>= 1) { cswap(r0, i0, j, k); cswap(r1, i1, j, k); }
            {
                bool desc = ((wrp & 1) == 0);
                if (desc ? (r0 < r1) : (r0 > r1)) {
                    unsigned long long t = r0; r0 = r1; r1 = t;
                }
#pragma unroll
                for (int j = 16; j > 0; j >>= 1) { cswap(r0, i0, j, 64); cswap(r1, i1, j, 64); }
            }
            P.s[i0] = r0;
            P.s[i1] = r1;
        }
        __syncthreads();

        for (int k = 128; k <= NPAD; k <<= 1) {
            for (int j = k >> 1; j >= 32; j >>= 1) {
#pragma unroll
                for (int e = 0; e < 2; ++e) {
                    int i = tid + e * 1024;
                    int ixj = i ^ j;
                    if (ixj > i) {
                        unsigned long long a = P.s[i], c = P.s[ixj];
                        bool desc = ((i & k) == 0);
                        if (desc ? (a < c) : (a > c)) { P.s[i] = c; P.s[ixj] = a; }
                    }
                }
                __syncthreads();
            }
            unsigned long long r0 = P.s[i0], r1 = P.s[i1];
#pragma unroll
            for (int j = 16; j > 0; j >>= 1) { cswap(r0, i0, j, k); cswap(r1, i1, j, k); }
            P.s[i0] = r0;
            P.s[i1] = r1;
            __syncthreads();
        }

        // gather top-256 candidates
        if (tid < MSEL) {
            unsigned long long key = P.s[tid];
            unsigned sb = (unsigned)(key >> 32);
            if (sb) {
                int idx = (int)(0xFFFFFFFFu - (unsigned)(key & 0xFFFFFFFFull));
                int gi = b * NN + idx;
                float4 bx = g_box4[gi];
                P.sy1[tid] = bx.x; P.sx1[tid] = bx.y; P.sy2[tid] = bx.z; P.sx2[tid] = bx.w;
                P.scl[tid] = g_cls[gi];
                P.ssc[tid] = __uint_as_float(sb);
            } else {
                P.sy1[tid] = 0.f; P.sx1[tid] = 0.f; P.sy2[tid] = 0.f; P.sx2[tid] = 0.f;
                P.scl[tid] = 0;
                P.ssc[tid] = -1.0f;
            }
        }
        __syncthreads();

        // suppression matrix
        {
            int wcol = wrp & 7;
            int ib = (wrp >> 3) * 64;
            int j = wcol * 32 + lane;
            float cfj = (float)P.scl[j];
            float jy1 = P.sy1[j] + 2.0f * cfj;
            float jx1 = P.sx1[j] + 2.0f * cfj;
            float jy2 = P.sy2[j] + 2.0f * cfj;
            float jx2 = P.sx2[j] + 2.0f * cfj;
            float jar = (jy2 - jy1) * (jx2 - jx1);
            for (int i = ib; i < ib + 64; ++i) {
                float cfi = (float)P.scl[i];
                float iy1 = P.sy1[i] + 2.0f * cfi;
                float ix1 = P.sx1[i] + 2.0f * cfi;
                float iy2 = P.sy2[i] + 2.0f * cfi;
                float ix2 = P.sx2[i] + 2.0f * cfi;
                float iar = (iy2 - iy1) * (ix2 - ix1);
                float yy1 = fmaxf(iy1, jy1);
                float xx1 = fmaxf(ix1, jx1);
                float yy2 = fminf(iy2, jy2);
                float xx2 = fminf(ix2, jx2);
                float inter = fmaxf(yy2 - yy1, 0.0f) * fmaxf(xx2 - xx1, 0.0f);
                float uni = iar + jar - inter;
                float iou = inter / fmaxf(uni, 1e-12f);
                unsigned bal = __ballot_sync(0xffffffffu, iou > 0.3f);
                if (lane == 0) P.Mm[i * 8 + wcol] = bal;
            }
        }
        __syncthreads();

        // warp-parallel fixpoint greedy
        if (wrp == 0) {
            unsigned rem[8] = {0, 0, 0, 0, 0, 0, 0, 0};
            int kc = 0;
            bool done = false;
            unsigned lower = (1u << lane) - 1u;
            for (int c = 0; c < 8 && !done; ++c) {
                int i = c * 32 + lane;
                unsigned row[8];
#pragma unroll
                for (int w = 0; w < 8; ++w) row[w] = P.Mm[i * 8 + w];
                bool v = P.ssc[i] > 0.0f;
                bool psup = (rem[c] >> lane) & 1u;
                unsigned wchunk = row[c] & lower;

                bool k = v && !psup;
                unsigned km = __ballot_sync(0xffffffffu, k);
                for (int it = 0; it < 40; ++it) {
                    bool kn = v && !psup && ((wchunk & km) == 0u);
                    unsigned km2 = __ballot_sync(0xffffffffu, kn);
                    if (km2 == km) break;
                    km = km2;
                }
                k = (km >> lane) & 1u;

                if (km) {
                    int cnt = __popc(km);
                    int need = MAXI - kc;
                    int pos = __popc(km & lower);
                    if (k && pos < need) {
                        float* dr = det + (b * MAXI + kc + pos) * 6;
                        dr[0] = P.sy1[i]; dr[1] = P.sx1[i]; dr[2] = P.sy2[i]; dr[3] = P.sx2[i];
                        dr[4] = (float)P.scl[i]; dr[5] = P.ssc[i];
                    }
                    if (cnt >= need) {
                        kc = MAXI;
                        done = true;
                    } else {
#pragma unroll
                        for (int w = 0; w < 8; ++w)
                            rem[w] |= __reduce_or_sync(0xffffffffu, k ? row[w] : 0u);
                        kc += cnt;
                    }
                }
            }
            if (lane == 0) {
                P.s_kc = kc;
                P.s_fb = (kc < MAXI && (unsigned)(P.s[MSEL] >> 32) != 0u) ? 1 : 0;
            }
        }
        __syncthreads();

        // rare fallback: serial warp NMS over full sorted list
        if (P.s_fb && wrp == 0) {
            int kc = 0;
            for (int i = 0; i < NN && kc < MAXI; ++i) {
                unsigned long long key = P.s[i];
                unsigned sb = (unsigned)(key >> 32);
                if (!sb) break;
                int idx = (int)(0xFFFFFFFFu - (unsigned)(key & 0xFFFFFFFFull));
                int gi = b * NN + idx;
                float4 bx = g_box4[gi];
                float y1 = bx.x, x1 = bx.y, y2 = bx.z, x2 = bx.w;
                float cf = (float)g_cls[gi];
                float score = __uint_as_float(sb);
                float oy1 = y1 + 2.0f * cf, ox1 = x1 + 2.0f * cf;
                float oy2 = y2 + 2.0f * cf, ox2 = x2 + 2.0f * cf;
                float ar = (oy2 - oy1) * (ox2 - ox1);
                bool sup = false;
                for (int j = lane; j < kc; j += 32) {
                    float yy1 = fmaxf(oy1, P.ky1[j]);
                    float xx1 = fmaxf(ox1, P.kx1[j]);
                    float yy2 = fminf(oy2, P.ky2[j]);
                    float xx2 = fminf(ox2, P.kx2[j]);
                    float inter = fmaxf(yy2 - yy1, 0.0f) * fmaxf(xx2 - xx1, 0.0f);
                    float uni = ar + P.kar[j] - inter;
                    float iou = inter / fmaxf(uni, 1e-12f);
                    sup |= (iou > 0.3f);
                }
                if (!__any_sync(0xffffffffu, sup)) {
                    if (lane == 0) {
                        P.ky1[kc] = oy1; P.kx1[kc] = ox1; P.ky2[kc] = oy2; P.kx2[kc] = ox2;
                        P.kar[kc] = ar;
                        float* dr = det + (b * MAXI + kc) * 6;
                        dr[0] = y1; dr[1] = x1; dr[2] = y2; dr[3] = x2;
                        dr[4] = cf; dr[5] = score;
                    }
                    kc++;
                }
                __syncwarp();
            }
            if (lane == 0) P.s_kc = kc;
        }
        __syncthreads();

        int kc = P.s_kc;
        for (int t = tid; t < (MAXI - kc) * 6; t += 1024)
            det[(b * MAXI + kc) * 6 + t] = 0.0f;
    }
    grid_bar(1);

    // ===================== Phase 3: mask (all blocks) =====================
    {
        P3& Q = *(P3*)smem_raw;
        for (int grp = bid; grp < 512; grp += GRID) {
            int b = grp >> 6;
            int h0 = (grp & 63) << 3;
            if (tid < 8) Q.nact[tid] = 0;
            __syncthreads();
            if (tid < 8 * MAXI) {
                int r = tid / MAXI;
                int d = tid - r * MAXI;
                const float* dr = det + (b * MAXI + d) * 6;
                float2 a = __ldcg((const float2*)dr);       // y1,x1
                float2 c = __ldcg((const float2*)(dr + 2)); // y2,x2
                float ys = ((float)(h0 + r) + 0.5f) * (1.0f / 512.0f);
                if (ys >= a.x && ys < c.x) {
                    int p = atomicAdd(&Q.nact[r], 1);
                    Q.ax1[r][p] = a.y;
                    Q.ax2[r][p] = c.y;
                }
            }
            __syncthreads();
            int r = tid >> 7;
            int g = tid & 127;
            int na = Q.nact[r];
            float xb = (float)(g * 4);
            float xs0 = (xb + 0.5f) * (1.0f / 512.0f);
            float xs1 = (xb + 1.5f) * (1.0f / 512.0f);
            float xs2 = (xb + 2.5f) * (1.0f / 512.0f);
            float xs3 = (xb + 3.5f) * (1.0f / 512.0f);
            float4 o = make_float4(0.f, 0.f, 0.f, 0.f);
            for (int j = 0; j < na; ++j) {
                float a = Q.ax1[r][j], c = Q.ax2[r][j];
                if (xs0 >= a && xs0 < c) o.x = 1.0f;
                if (xs1 >= a && xs1 < c) o.y = 1.0f;
                if (xs2 >= a && xs2 < c) o.z = 1.0f;
                if (xs3 >= a && xs3 < c) o.w = 1.0f;
            }
            ((float4*)(mask + ((long long)(b * HH + h0 + r)) * WW))[g] = o;
            __syncthreads();  // protect shared reuse next iteration
        }
    }
}

// ---------------------------------------------------------------------------
extern "C" void kernel_launch(void* const* d_in, const int* in_sizes, int n_in,
                              void* d_out, int out_size) {
    const float* rois = (const float*)d_in[0];
    const float* probs = (const float*)d_in[1];
    const float* deltas = (const float*)d_in[2];
    const float* stdv = (const float*)d_in[3];
    float* det = (float*)d_out;                   // [B,100,6]
    float* mask = (float*)d_out + BB * MAXI * 6;  // [B,512,512]

    fused_all<<<GRID, 1024>>>(rois, probs, deltas, stdv, det, mask);
}

// round 7
// speedup vs baseline: 1.5509x; 1.5509x over previous
#include <cuda_runtime.h>

#define BB 8
#define NN 2000
#define CC 81
#define MAXI 100
#define HH 512
#define WW 512
#define MSEL 256
#define GRID 128

// scratch (device globals: no allocation allowed)
__device__ float4 g_box4[BB * NN];
__device__ int g_cls[BB * NN];
__device__ unsigned long long g_key[BB * 2048];   // 16 sorted runs of 128 per batch
__device__ unsigned g_M[BB * 256 * 8];            // suppression matrix per batch
__device__ unsigned g_bar[4];                     // monotone barrier counters

struct SM {
    unsigned long long K[2048];                                   // 16KB
    float sy1[MSEL], sx1[MSEL], sy2[MSEL], sx2[MSEL], ssc[MSEL];  // 5KB
    int scl[MSEL];                                                // 1KB
    float ky1[MAXI], kx1[MAXI], ky2[MAXI], kx2[MAXI], kar[MAXI];  // 2KB
    int nvalid, s_kc, s_fb;
};
struct P3S { float ax1[8][MAXI], ax2[8][MAXI]; int nact[8]; };

__device__ __forceinline__ void cswap(unsigned long long& v, int i, int j, int k) {
    unsigned long long pv = __shfl_xor_sync(0xffffffffu, v, j);
    bool take_max = (((i & k) == 0) ^ ((i & j) != 0));
    bool pick = take_max ? (pv > v) : (pv < v);
    if (pick) v = pv;
}

// monotone grid barrier: correct across arbitrarily many sequential launches
__device__ __forceinline__ void grid_bar(int i) {
    __threadfence();
    __syncthreads();
    if (threadIdx.x == 0) {
        unsigned t = atomicAdd(&g_bar[i], 1u);
        unsigned target = (t / GRID + 1u) * GRID;
        while (*(volatile unsigned*)&g_bar[i] < target) {}
    }
    __syncthreads();
}

__global__ void __launch_bounds__(1024, 1)
fused_all(const float* __restrict__ rois,
          const float* __restrict__ probs,
          const float* __restrict__ deltas,
          const float* __restrict__ stdv,
          float* __restrict__ det,
          float* __restrict__ mask) {
    __shared__ __align__(16) char smraw[sizeof(SM)];
    SM& S = *(SM*)smraw;
    int tid = threadIdx.x;
    int lane = tid & 31;
    int wrp = tid >> 5;
    int bid = blockIdx.x;

    // ============ Phase 1: refine + slice sort (128 blocks, slice=128) ============
    {
        int b = bid >> 4, s = bid & 15;
        int n0 = s * 128 + wrp * 4;  // warp's 4 proposals
        if (n0 < NN) {
            float best[4];
            int bc[4];
#pragma unroll
            for (int q = 0; q < 4; ++q) {
                const float* p = probs + (long long)(b * NN + n0 + q) * CC;
                float b0 = p[lane];
                float b1 = p[lane + 32];
                float b2 = (lane + 64 < CC) ? p[lane + 64] : -1.0f;
                int c = lane;
                float bst = b0;
                if (b1 > bst) { bst = b1; c = lane + 32; }
                if (b2 > bst) { bst = b2; c = lane + 64; }
                best[q] = bst;
                bc[q] = c;
            }
#pragma unroll
            for (int q = 0; q < 4; ++q) {
#pragma unroll
                for (int o = 16; o; o >>= 1) {
                    float ov = __shfl_down_sync(0xffffffffu, best[q], o);
                    int oc = __shfl_down_sync(0xffffffffu, bc[q], o);
                    if (ov > best[q] || (ov == best[q] && oc < bc[q])) { best[q] = ov; bc[q] = oc; }
                }
                best[q] = __shfl_sync(0xffffffffu, best[q], 0);
                bc[q] = __shfl_sync(0xffffffffu, bc[q], 0);
            }
            if (lane < 4) {
                int n = n0 + lane;
                int gw = b * NN + n;
                float bst = best[lane];
                int c = bc[lane];
                float4 dd = *(const float4*)(deltas + ((long long)gw * CC + c) * 4);
                float dy = dd.x * stdv[0];
                float dx = dd.y * stdv[1];
                float dh = dd.z * stdv[2];
                float dw = dd.w * stdv[3];
                float4 rr = *(const float4*)(rois + gw * 4);
                float y1 = rr.x, x1 = rr.y, y2 = rr.z, x2 = rr.w;
                float h = y2 - y1, w2 = x2 - x1;
                float cy = y1 + 0.5f * h + dy * h;
                float cx = x1 + 0.5f * w2 + dx * w2;
                h = h * expf(dh);
                w2 = w2 * expf(dw);
                float4 nb;
                nb.x = fminf(fmaxf(cy - 0.5f * h, 0.0f), 1.0f);
                nb.y = fminf(fmaxf(cx - 0.5f * w2, 0.0f), 1.0f);
                nb.z = fminf(fmaxf(cy + 0.5f * h, 0.0f), 1.0f);
                nb.w = fminf(fmaxf(cx + 0.5f * w2, 0.0f), 1.0f);
                g_box4[gw] = nb;
                g_cls[gw] = c;
                bool valid = (c > 0) && (bst >= 0.05f);
                S.K[wrp * 4 + lane] =
                    valid ? ((((unsigned long long)__float_as_uint(bst)) << 32) |
                             (unsigned long long)(0xFFFFFFFFu - (unsigned)n))
                          : 0ull;
            }
        } else {
            if (lane < 4) S.K[wrp * 4 + lane] = 0ull;
        }
        __syncthreads();

        // sort the 128 slice keys descending (2 warps, registers + 2 smem passes)
        if (tid < 64) {
            int w2 = tid >> 5, l = tid & 31;
            int i0 = w2 * 64 + l, i1 = i0 + 32;
            unsigned long long r0 = S.K[i0], r1 = S.K[i1];
#pragma unroll
            for (int k = 2; k <= 32; k <<= 1)
#pragma unroll
                for (int j = k >> 1; j > 0; j >>= 1) { cswap(r0, i0, j, k); cswap(r1, i1, j, k); }
            {   // k=64: j=32 is r0<->r1; direction alternates by group
                bool desc = ((w2 & 1) == 0);
                if (desc ? (r0 < r1) : (r0 > r1)) {
                    unsigned long long t = r0; r0 = r1; r1 = t;
                }
#pragma unroll
                for (int j = 16; j > 0; j >>= 1) { cswap(r0, i0, j, 64); cswap(r1, i1, j, 64); }
            }
            S.K[i0] = r0;
            S.K[i1] = r1;
        }
        __syncthreads();
        if (tid < 64) {  // k=128, j=64 (desc everywhere)
            unsigned long long a = S.K[tid], c = S.K[tid + 64];
            if (a < c) { S.K[tid] = c; S.K[tid + 64] = a; }
        }
        __syncthreads();
        if (tid < 64) {  // k=128, j=32
            int i = (tid >> 5) * 64 + (tid & 31);
            unsigned long long a = S.K[i], c = S.K[i + 32];
            if (a < c) { S.K[i] = c; S.K[i + 32] = a; }
        }
        __syncthreads();
        if (tid < 64) {  // k=128, j=16..1 + write run to global
            int w2 = tid >> 5, l = tid & 31;
            int i0 = w2 * 64 + l, i1 = i0 + 32;
            unsigned long long r0 = S.K[i0], r1 = S.K[i1];
#pragma unroll
            for (int j = 16; j > 0; j >>= 1) { cswap(r0, i0, j, 128); cswap(r1, i1, j, 128); }
            g_key[b * 2048 + s * 128 + i0] = r0;
            g_key[b * 2048 + s * 128 + i1] = r1;
        }
    }
    grid_bar(0);

    // ============ Phase 2B/2C: merge 16 runs -> top-256; build matrix slice ============
    // 64 blocks: b = bid>>3, s2 = bid&7. Merge is redundant per batch (keeps sel in smem).
    if (bid < 64) {
        int b = bid >> 3, s2 = bid & 7;
        if (tid == 0) S.nvalid = 0;
        __syncthreads();
        unsigned long long k0 = g_key[b * 2048 + tid];
        unsigned long long k1 = g_key[b * 2048 + 1024 + tid];
        S.K[tid] = k0;
        S.K[1024 + tid] = k1;
        unsigned m0 = __ballot_sync(0xffffffffu, k0 != 0ull);
        unsigned m1 = __ballot_sync(0xffffffffu, k1 != 0ull);
        if (lane == 0) atomicAdd(&S.nvalid, __popc(m0) + __popc(m1));
        __syncthreads();

        // Round 1: 16 runs(128) -> 8 runs(256), FULL merge
        {
            int g = tid >> 7, i = tid & 127, base = g * 256;
            unsigned long long a = S.K[base + i], c = S.K[base + 255 - i];
            unsigned long long hi = a > c ? a : c, lo = a > c ? c : a;
            __syncthreads();
            S.K[base + i] = hi;
            S.K[base + 128 + i] = lo;
        }
        __syncthreads();
        for (int j = 64; j > 0; j >>= 1) {
            int seg = tid >> 7, cid = tid & 127;
            int i2 = ((cid & ~(j - 1)) << 1) | (cid & (j - 1));
            int a1 = seg * 256 + i2;
            unsigned long long x = S.K[a1], y = S.K[a1 + j];
            if (x < y) { S.K[a1] = y; S.K[a1 + j] = x; }
            __syncthreads();
        }
        // Round 2: 8 -> 4 (top-256 kept, compacted)
        {
            int g = tid >> 8, i = tid & 255;
            unsigned long long a = S.K[(2 * g) * 256 + i];
            unsigned long long c = S.K[(2 * g + 1) * 256 + 255 - i];
            unsigned long long L = a > c ? a : c;
            __syncthreads();
            S.K[g * 256 + i] = L;
        }
        __syncthreads();
        for (int j = 128; j > 0; j >>= 1) {
            if (tid < 512) {
                int seg = tid >> 7, cid = tid & 127;
                int i2 = ((cid & ~(j - 1)) << 1) | (cid & (j - 1));
                int a1 = seg * 256 + i2;
                unsigned long long x = S.K[a1], y = S.K[a1 + j];
                if (x < y) { S.K[a1] = y; S.K[a1 + j] = x; }
            }
            __syncthreads();
        }
        // Round 3: 4 -> 2
        {
            unsigned long long L = 0;
            int g = tid >> 8, i = tid & 255;
            if (tid < 512) {
                unsigned long long a = S.K[(2 * g) * 256 + i];
                unsigned long long c = S.K[(2 * g + 1) * 256 + 255 - i];
                L = a > c ? a : c;
            }
            __syncthreads();
            if (tid < 512) S.K[g * 256 + i] = L;
        }
        __syncthreads();
        for (int j = 128; j > 0; j >>= 1) {
            if (tid < 256) {
                int seg = tid >> 7, cid = tid & 127;
                int i2 = ((cid & ~(j - 1)) << 1) | (cid & (j - 1));
                int a1 = seg * 256 + i2;
                unsigned long long x = S.K[a1], y = S.K[a1 + j];
                if (x < y) { S.K[a1] = y; S.K[a1 + j] = x; }
            }
            __syncthreads();
        }
        // Round 4: 2 -> 1 (final top-256 descending in K[0..256))
        {
            unsigned long long L = 0;
            if (tid < 256) {
                unsigned long long a = S.K[tid];
                unsigned long long c = S.K[511 - tid];
                L = a > c ? a : c;
            }
            __syncthreads();
            if (tid < 256) S.K[tid] = L;
        }
        __syncthreads();
        for (int j = 128; j > 0; j >>= 1) {
            if (tid < 128) {
                int cid = tid;
                int i2 = ((cid & ~(j - 1)) << 1) | (cid & (j - 1));
                unsigned long long x = S.K[i2], y = S.K[i2 + j];
                if (x < y) { S.K[i2] = y; S.K[i2 + j] = x; }
            }
            __syncthreads();
        }

        // gather selected candidate boxes
        if (tid < MSEL) {
            unsigned long long key = S.K[tid];
            unsigned sb = (unsigned)(key >> 32);
            if (sb) {
                int idx = (int)(0xFFFFFFFFu - (unsigned)(key & 0xFFFFFFFFull));
                int gi = b * NN + idx;
                float4 bx = g_box4[gi];
                S.sy1[tid] = bx.x; S.sx1[tid] = bx.y; S.sy2[tid] = bx.z; S.sx2[tid] = bx.w;
                S.scl[tid] = g_cls[gi];
                S.ssc[tid] = __uint_as_float(sb);
            } else {
                S.sy1[tid] = 0.f; S.sx1[tid] = 0.f; S.sy2[tid] = 0.f; S.sx2[tid] = 0.f;
                S.scl[tid] = 0;
                S.ssc[tid] = -1.0f;
            }
        }
        __syncthreads();

        // matrix slice: warp -> row r = s2*32 + wrp, all 8 column-words
        {
            int r = s2 * 32 + wrp;
            float cfr = (float)S.scl[r];
            float ry1 = S.sy1[r] + 2.0f * cfr;
            float rx1 = S.sx1[r] + 2.0f * cfr;
            float ry2 = S.sy2[r] + 2.0f * cfr;
            float rx2 = S.sx2[r] + 2.0f * cfr;
            float rar = (ry2 - ry1) * (rx2 - rx1);
#pragma unroll
            for (int t = 0; t < 8; ++t) {
                int j = t * 32 + lane;
                float cfj = (float)S.scl[j];
                float jy1 = S.sy1[j] + 2.0f * cfj;
                float jx1 = S.sx1[j] + 2.0f * cfj;
                float jy2 = S.sy2[j] + 2.0f * cfj;
                float jx2 = S.sx2[j] + 2.0f * cfj;
                float jar = (jy2 - jy1) * (jx2 - jx1);
                float yy1 = fmaxf(ry1, jy1);
                float xx1 = fmaxf(rx1, jx1);
                float yy2 = fminf(ry2, jy2);
                float xx2 = fminf(rx2, jx2);
                float inter = fmaxf(yy2 - yy1, 0.0f) * fmaxf(xx2 - xx1, 0.0f);
                float uni = rar + jar - inter;
                float iou = inter / fmaxf(uni, 1e-12f);
                unsigned bal = __ballot_sync(0xffffffffu, iou > 0.3f);
                if (lane == 0) g_M[(b * 256 + r) * 8 + t] = bal;
            }
        }
    }
    grid_bar(1);

    // ============ Phase 2D: greedy NMS (8 blocks: bid = b*8, sel still in smem) ============
    if (bid < 64 && (bid & 7) == 0) {
        int b = bid >> 3;
        if (wrp == 0) {
            unsigned rem[8] = {0, 0, 0, 0, 0, 0, 0, 0};
            int kc = 0;
            bool done = false;
            unsigned lower = (1u << lane) - 1u;
            for (int c = 0; c < 8 && !done; ++c) {
                int i = c * 32 + lane;
                unsigned row[8];
#pragma unroll
                for (int w = 0; w < 8; ++w) row[w] = __ldcg(&g_M[(b * 256 + i) * 8 + w]);
                bool v = S.ssc[i] > 0.0f;
                bool psup = (rem[c] >> lane) & 1u;
                unsigned wchunk = row[c] & lower;

                bool k = v && !psup;
                unsigned km = __ballot_sync(0xffffffffu, k);
                for (int it = 0; it < 40; ++it) {
                    bool kn = v && !psup && ((wchunk & km) == 0u);
                    unsigned km2 = __ballot_sync(0xffffffffu, kn);
                    if (km2 == km) break;
                    km = km2;
                }
                k = (km >> lane) & 1u;

                if (km) {
                    int cnt = __popc(km);
                    int need = MAXI - kc;
                    int pos = __popc(km & lower);
                    if (k && pos < need) {
                        float* dr = det + (b * MAXI + kc + pos) * 6;
                        dr[0] = S.sy1[i]; dr[1] = S.sx1[i]; dr[2] = S.sy2[i]; dr[3] = S.sx2[i];
                        dr[4] = (float)S.scl[i]; dr[5] = S.ssc[i];
                    }
                    if (cnt >= need) {
                        kc = MAXI;
                        done = true;
                    } else {
#pragma unroll
                        for (int w = 0; w < 8; ++w)
                            rem[w] |= __reduce_or_sync(0xffffffffu, k ? row[w] : 0u);
                        kc += cnt;
                    }
                }
            }
            if (lane == 0) {
                S.s_kc = kc;
                S.s_fb = (kc < MAXI && S.nvalid > MSEL) ? 1 : 0;
            }
        }
        __syncthreads();

        // rare fallback: serial warp NMS over virtual 16-way merged stream
        if (S.s_fb && wrp == 0) {
            int kc = 0;
            int hp[16];
#pragma unroll
            for (int r = 0; r < 16; ++r) hp[r] = 0;
            for (int iter = 0; iter < NN && kc < MAXI; ++iter) {
                unsigned long long bk = 0;
                int br = -1;
#pragma unroll
                for (int r = 0; r < 16; ++r) {
                    if (hp[r] < 128) {
                        unsigned long long kk = __ldg(&g_key[b * 2048 + r * 128 + hp[r]]);
                        if (kk > bk) { bk = kk; br = r; }
                    }
                }
                if (bk == 0) break;
                hp[br]++;
                int idx = (int)(0xFFFFFFFFu - (unsigned)(bk & 0xFFFFFFFFull));
                int gi = b * NN + idx;
                float4 bx = g_box4[gi];
                float y1 = bx.x, x1 = bx.y, y2 = bx.z, x2 = bx.w;
                float cf = (float)g_cls[gi];
                float score = __uint_as_float((unsigned)(bk >> 32));
                float oy1 = y1 + 2.0f * cf, ox1 = x1 + 2.0f * cf;
                float oy2 = y2 + 2.0f * cf, ox2 = x2 + 2.0f * cf;
                float ar = (oy2 - oy1) * (ox2 - ox1);
                bool sup = false;
                for (int j = lane; j < kc; j += 32) {
                    float yy1 = fmaxf(oy1, S.ky1[j]);
                    float xx1 = fmaxf(ox1, S.kx1[j]);
                    float yy2 = fminf(oy2, S.ky2[j]);
                    float xx2 = fminf(ox2, S.kx2[j]);
                    float inter = fmaxf(yy2 - yy1, 0.0f) * fmaxf(xx2 - xx1, 0.0f);
                    float uni = ar + S.kar[j] - inter;
                    float iou = inter / fmaxf(uni, 1e-12f);
                    sup |= (iou > 0.3f);
                }
                if (!__any_sync(0xffffffffu, sup)) {
                    if (lane == 0) {
                        S.ky1[kc] = oy1; S.kx1[kc] = ox1; S.ky2[kc] = oy2; S.kx2[kc] = ox2;
                        S.kar[kc] = ar;
                        float* dr = det + (b * MAXI + kc) * 6;
                        dr[0] = y1; dr[1] = x1; dr[2] = y2; dr[3] = x2;
                        dr[4] = cf; dr[5] = score;
                    }
                    kc++;
                }
                __syncwarp();
            }
            if (lane == 0) S.s_kc = kc;
        }
        __syncthreads();

        int kc = S.s_kc;
        for (int t = tid; t < (MAXI - kc) * 6; t += 1024)
            det[(b * MAXI + kc) * 6 + t] = 0.0f;
    }
    grid_bar(2);

    // ============ Phase 3: mask (all blocks; 512 row-groups) ============
    {
        P3S& Q = *(P3S*)smraw;
        for (int grp = bid; grp < 512; grp += GRID) {
            int b = grp >> 6;
            int h0 = (grp & 63) << 3;
            if (tid < 8) Q.nact[tid] = 0;
            __syncthreads();
            if (tid < 8 * MAXI) {
                int r = tid / MAXI;
                int d = tid - r * MAXI;
                const float* dr = det + (b * MAXI + d) * 6;
                float2 a = __ldcg((const float2*)dr);        // y1,x1
                float2 c = __ldcg((const float2*)(dr + 2));  // y2,x2
                float ys = ((float)(h0 + r) + 0.5f) * (1.0f / 512.0f);
                if (ys >= a.x && ys < c.x) {
                    int p = atomicAdd(&Q.nact[r], 1);
                    Q.ax1[r][p] = a.y;
                    Q.ax2[r][p] = c.y;
                }
            }
            __syncthreads();
            int r = tid >> 7;
            int g = tid & 127;
            int na = Q.nact[r];
            float xb = (float)(g * 4);
            float xs0 = (xb + 0.5f) * (1.0f / 512.0f);
            float xs1 = (xb + 1.5f) * (1.0f / 512.0f);
            float xs2 = (xb + 2.5f) * (1.0f / 512.0f);
            float xs3 = (xb + 3.5f) * (1.0f / 512.0f);
            float4 o = make_float4(0.f, 0.f, 0.f, 0.f);
            for (int j = 0; j < na; ++j) {
                float a = Q.ax1[r][j], c = Q.ax2[r][j];
                if (xs0 >= a && xs0 < c) o.x = 1.0f;
                if (xs1 >= a && xs1 < c) o.y = 1.0f;
                if (xs2 >= a && xs2 < c) o.z = 1.0f;
                if (xs3 >= a && xs3 < c) o.w = 1.0f;
            }
            ((float4*)(mask + ((long long)(b * HH + h0 + r)) * WW))[g] = o;
            __syncthreads();  // protect shared reuse next iteration
        }
    }
}

// ---------------------------------------------------------------------------
extern "C" void kernel_launch(void* const* d_in, const int* in_sizes, int n_in,
                              void* d_out, int out_size) {
    const float* rois = (const float*)d_in[0];
    const float* probs = (const float*)d_in[1];
    const float* deltas = (const float*)d_in[2];
    const float* stdv = (const float*)d_in[3];
    float* det = (float*)d_out;                   // [B,100,6]
    float* mask = (float*)d_out + BB * MAXI * 6;  // [B,512,512]

    fused_all<<<GRID, 1024>>>(rois, probs, deltas, stdv, det, mask);
}

// round 8
// speedup vs baseline: 1.6837x; 1.0856x over previous
#include <cuda_runtime.h>

#define BB 8
#define NN 2000
#define CC 81
#define MAXI 100
#define HH 512
#define WW 512
#define MSEL 256
#define GRID 128

// scratch (device globals: no allocation allowed)
__device__ float4 g_box4[BB * NN];
__device__ int g_cls[BB * NN];
__device__ unsigned long long g_key[BB * 2048];   // 16 sorted runs of 128 per batch
__device__ unsigned g_M[BB * 256 * 8];            // suppression matrix per batch
__device__ unsigned g_bar[4];  // [0]=main bar [1]=matrix [2]=det [3]=zero (monotone)

struct SM {
    unsigned long long K[2048];                                   // 16KB (reused as matrix cache)
    float sy1[MSEL], sx1[MSEL], sy2[MSEL], sx2[MSEL], ssc[MSEL];  // 5KB
    int scl[MSEL];                                                // 1KB
    float ky1[MAXI], kx1[MAXI], ky2[MAXI], kx2[MAXI], kar[MAXI];  // 2KB
    int nvalid, s_kc, s_fb;
    int round;
};

__device__ __forceinline__ void cswap(unsigned long long& v, int i, int j, int k) {
    unsigned long long pv = __shfl_xor_sync(0xffffffffu, v, j);
    bool take_max = (((i & k) == 0) ^ ((i & j) != 0));
    bool pick = take_max ? (pv > v) : (pv < v);
    if (pick) v = pv;
}

// wait until monotone counter g_bar[i] >= target (thread 0 polls, block-wide release)
__device__ __forceinline__ void wait_ge(int i, unsigned target) {
    if (threadIdx.x == 0) {
        while (*(volatile unsigned*)&g_bar[i] < target) {}
    }
    __syncthreads();
}

__global__ void __launch_bounds__(1024, 1)
fused_all(const float* __restrict__ rois,
          const float* __restrict__ probs,
          const float* __restrict__ deltas,
          const float* __restrict__ stdv,
          float* __restrict__ det,
          float* __restrict__ mask) {
    __shared__ __align__(16) char smraw[sizeof(SM)];
    SM& S = *(SM*)smraw;
    int tid = threadIdx.x;
    int lane = tid & 31;
    int wrp = tid >> 5;
    int bid = blockIdx.x;

    // ============ Phase 1: refine + slice sort (128 blocks, slice=128) ============
    {
        int b = bid >> 4, s = bid & 15;
        int n0 = s * 128 + wrp * 4;  // warp's 4 proposals
        if (n0 < NN) {
            float best[4];
            int bc[4];
#pragma unroll
            for (int q = 0; q < 4; ++q) {
                const float* p = probs + (long long)(b * NN + n0 + q) * CC;
                float b0 = p[lane];
                float b1 = p[lane + 32];
                float b2 = (lane + 64 < CC) ? p[lane + 64] : -1.0f;
                int c = lane;
                float bst = b0;
                if (b1 > bst) { bst = b1; c = lane + 32; }
                if (b2 > bst) { bst = b2; c = lane + 64; }
                best[q] = bst;
                bc[q] = c;
            }
#pragma unroll
            for (int q = 0; q < 4; ++q) {
#pragma unroll
                for (int o = 16; o; o >>= 1) {
                    float ov = __shfl_down_sync(0xffffffffu, best[q], o);
                    int oc = __shfl_down_sync(0xffffffffu, bc[q], o);
                    if (ov > best[q] || (ov == best[q] && oc < bc[q])) { best[q] = ov; bc[q] = oc; }
                }
                best[q] = __shfl_sync(0xffffffffu, best[q], 0);
                bc[q] = __shfl_sync(0xffffffffu, bc[q], 0);
            }
            if (lane < 4) {
                int n = n0 + lane;
                int gw = b * NN + n;
                float bst = best[lane];
                int c = bc[lane];
                float4 dd = *(const float4*)(deltas + ((long long)gw * CC + c) * 4);
                float dy = dd.x * stdv[0];
                float dx = dd.y * stdv[1];
                float dh = dd.z * stdv[2];
                float dw = dd.w * stdv[3];
                float4 rr = *(const float4*)(rois + gw * 4);
                float y1 = rr.x, x1 = rr.y, y2 = rr.z, x2 = rr.w;
                float h = y2 - y1, w2 = x2 - x1;
                float cy = y1 + 0.5f * h + dy * h;
                float cx = x1 + 0.5f * w2 + dx * w2;
                h = h * expf(dh);
                w2 = w2 * expf(dw);
                float4 nb;
                nb.x = fminf(fmaxf(cy - 0.5f * h, 0.0f), 1.0f);
                nb.y = fminf(fmaxf(cx - 0.5f * w2, 0.0f), 1.0f);
                nb.z = fminf(fmaxf(cy + 0.5f * h, 0.0f), 1.0f);
                nb.w = fminf(fmaxf(cx + 0.5f * w2, 0.0f), 1.0f);
                g_box4[gw] = nb;
                g_cls[gw] = c;
                bool valid = (c > 0) && (bst >= 0.05f);
                S.K[wrp * 4 + lane] =
                    valid ? ((((unsigned long long)__float_as_uint(bst)) << 32) |
                             (unsigned long long)(0xFFFFFFFFu - (unsigned)n))
                          : 0ull;
            }
        } else {
            if (lane < 4) S.K[wrp * 4 + lane] = 0ull;
        }
        __syncthreads();

        // sort the 128 slice keys descending (2 warps, registers + 2 smem passes)
        if (tid < 64) {
            int w2 = tid >> 5, l = tid & 31;
            int i0 = w2 * 64 + l, i1 = i0 + 32;
            unsigned long long r0 = S.K[i0], r1 = S.K[i1];
#pragma unroll
            for (int k = 2; k <= 32; k <<= 1)
#pragma unroll
                for (int j = k >> 1; j > 0; j >>= 1) { cswap(r0, i0, j, k); cswap(r1, i1, j, k); }
            {   // k=64: j=32 is r0<->r1; direction alternates by group
                bool desc = ((w2 & 1) == 0);
                if (desc ? (r0 < r1) : (r0 > r1)) {
                    unsigned long long t = r0; r0 = r1; r1 = t;
                }
#pragma unroll
                for (int j = 16; j > 0; j >>= 1) { cswap(r0, i0, j, 64); cswap(r1, i1, j, 64); }
            }
            S.K[i0] = r0;
            S.K[i1] = r1;
        }
        __syncthreads();
        if (tid < 64) {  // k=128, j=64 (desc everywhere)
            unsigned long long a = S.K[tid], c = S.K[tid + 64];
            if (a < c) { S.K[tid] = c; S.K[tid + 64] = a; }
        }
        __syncthreads();
        if (tid < 64) {  // k=128, j=32
            int i = (tid >> 5) * 64 + (tid & 31);
            unsigned long long a = S.K[i], c = S.K[i + 32];
            if (a < c) { S.K[i] = c; S.K[i + 32] = a; }
        }
        __syncthreads();
        if (tid < 64) {  // k=128, j=16..1 + write run to global
            int w2 = tid >> 5, l = tid & 31;
            int i0 = w2 * 64 + l, i1 = i0 + 32;
            unsigned long long r0 = S.K[i0], r1 = S.K[i1];
#pragma unroll
            for (int j = 16; j > 0; j >>= 1) { cswap(r0, i0, j, 128); cswap(r1, i1, j, 128); }
            g_key[b * 2048 + s * 128 + i0] = r0;
            g_key[b * 2048 + s * 128 + i1] = r1;
        }
    }

    // ---- main grid barrier; every block learns its replay round ----
    __threadfence();
    __syncthreads();
    if (tid == 0) {
        unsigned t = atomicAdd(&g_bar[0], 1u);
        unsigned round = t / GRID;
        S.round = (int)round;
        unsigned target = (round + 1u) * GRID;
        while (*(volatile unsigned*)&g_bar[0] < target) {}
    }
    __syncthreads();
    unsigned round = (unsigned)S.round;

    // ============ Phase 2B/2C: merge -> top-256; matrix slice (blocks 0..63) ============
    if (bid < 64) {
        int b = bid >> 3, s2 = bid & 7;
        if (tid == 0) S.nvalid = 0;
        __syncthreads();
        unsigned long long k0 = g_key[b * 2048 + tid];
        unsigned long long k1 = g_key[b * 2048 + 1024 + tid];
        S.K[tid] = k0;
        S.K[1024 + tid] = k1;
        unsigned m0 = __ballot_sync(0xffffffffu, k0 != 0ull);
        unsigned m1 = __ballot_sync(0xffffffffu, k1 != 0ull);
        if (lane == 0) atomicAdd(&S.nvalid, __popc(m0) + __popc(m1));
        __syncthreads();

        // Round 1: 16 runs(128) -> 8 runs(256), FULL merge
        {
            int g = tid >> 7, i = tid & 127, base = g * 256;
            unsigned long long a = S.K[base + i], c = S.K[base + 255 - i];
            unsigned long long hi = a > c ? a : c, lo = a > c ? c : a;
            __syncthreads();
            S.K[base + i] = hi;
            S.K[base + 128 + i] = lo;
        }
        __syncthreads();
        for (int j = 64; j > 0; j >>= 1) {
            int seg = tid >> 7, cid = tid & 127;
            int i2 = ((cid & ~(j - 1)) << 1) | (cid & (j - 1));
            int a1 = seg * 256 + i2;
            unsigned long long x = S.K[a1], y = S.K[a1 + j];
            if (x < y) { S.K[a1] = y; S.K[a1 + j] = x; }
            __syncthreads();
        }
        // Round 2: 8 -> 4 (top-256 kept)
        {
            int g = tid >> 8, i = tid & 255;
            unsigned long long a = S.K[(2 * g) * 256 + i];
            unsigned long long c = S.K[(2 * g + 1) * 256 + 255 - i];
            unsigned long long L = a > c ? a : c;
            __syncthreads();
            S.K[g * 256 + i] = L;
        }
        __syncthreads();
        for (int j = 128; j > 0; j >>= 1) {
            if (tid < 512) {
                int seg = tid >> 7, cid = tid & 127;
                int i2 = ((cid & ~(j - 1)) << 1) | (cid & (j - 1));
                int a1 = seg * 256 + i2;
                unsigned long long x = S.K[a1], y = S.K[a1 + j];
                if (x < y) { S.K[a1] = y; S.K[a1 + j] = x; }
            }
            __syncthreads();
        }
        // Round 3: 4 -> 2
        {
            unsigned long long L = 0;
            int g = tid >> 8, i = tid & 255;
            if (tid < 512) {
                unsigned long long a = S.K[(2 * g) * 256 + i];
                unsigned long long c = S.K[(2 * g + 1) * 256 + 255 - i];
                L = a > c ? a : c;
            }
            __syncthreads();
            if (tid < 512) S.K[g * 256 + i] = L;
        }
        __syncthreads();
        for (int j = 128; j > 0; j >>= 1) {
            if (tid < 256) {
                int seg = tid >> 7, cid = tid & 127;
                int i2 = ((cid & ~(j - 1)) << 1) | (cid & (j - 1));
                int a1 = seg * 256 + i2;
                unsigned long long x = S.K[a1], y = S.K[a1 + j];
                if (x < y) { S.K[a1] = y; S.K[a1 + j] = x; }
            }
            __syncthreads();
        }
        // Round 4: 2 -> 1 (final top-256 descending in K[0..256))
        {
            unsigned long long L = 0;
            if (tid < 256) {
                unsigned long long a = S.K[tid];
                unsigned long long c = S.K[511 - tid];
                L = a > c ? a : c;
            }
            __syncthreads();
            if (tid < 256) S.K[tid] = L;
        }
        __syncthreads();
        for (int j = 128; j > 0; j >>= 1) {
            if (tid < 128) {
                int cid = tid;
                int i2 = ((cid & ~(j - 1)) << 1) | (cid & (j - 1));
                unsigned long long x = S.K[i2], y = S.K[i2 + j];
                if (x < y) { S.K[i2] = y; S.K[i2 + j] = x; }
            }
            __syncthreads();
        }

        // gather selected candidate boxes
        if (tid < MSEL) {
            unsigned long long key = S.K[tid];
            unsigned sb = (unsigned)(key >> 32);
            if (sb) {
                int idx = (int)(0xFFFFFFFFu - (unsigned)(key & 0xFFFFFFFFull));
                int gi = b * NN + idx;
                float4 bx = g_box4[gi];
                S.sy1[tid] = bx.x; S.sx1[tid] = bx.y; S.sy2[tid] = bx.z; S.sx2[tid] = bx.w;
                S.scl[tid] = g_cls[gi];
                S.ssc[tid] = __uint_as_float(sb);
            } else {
                S.sy1[tid] = 0.f; S.sx1[tid] = 0.f; S.sy2[tid] = 0.f; S.sx2[tid] = 0.f;
                S.scl[tid] = 0;
                S.ssc[tid] = -1.0f;
            }
        }
        __syncthreads();

        // matrix slice: warp -> row r = s2*32 + wrp, all 8 column-words
        {
            int r = s2 * 32 + wrp;
            float cfr = (float)S.scl[r];
            float ry1 = S.sy1[r] + 2.0f * cfr;
            float rx1 = S.sx1[r] + 2.0f * cfr;
            float ry2 = S.sy2[r] + 2.0f * cfr;
            float rx2 = S.sx2[r] + 2.0f * cfr;
            float rar = (ry2 - ry1) * (rx2 - rx1);
#pragma unroll
            for (int t = 0; t < 8; ++t) {
                int j = t * 32 + lane;
                float cfj = (float)S.scl[j];
                float jy1 = S.sy1[j] + 2.0f * cfj;
                float jx1 = S.sx1[j] + 2.0f * cfj;
                float jy2 = S.sy2[j] + 2.0f * cfj;
                float jx2 = S.sx2[j] + 2.0f * cfj;
                float jar = (jy2 - jy1) * (jx2 - jx1);
                float yy1 = fmaxf(ry1, jy1);
                float xx1 = fmaxf(rx1, jx1);
                float yy2 = fminf(ry2, jy2);
                float xx2 = fminf(rx2, jx2);
                float inter = fmaxf(yy2 - yy1, 0.0f) * fmaxf(xx2 - xx1, 0.0f);
                float uni = rar + jar - inter;
                float iou = inter / fmaxf(uni, 1e-12f);
                unsigned bal = __ballot_sync(0xffffffffu, iou > 0.3f);
                if (lane == 0) g_M[(b * 256 + r) * 8 + t] = bal;
            }
        }
        __threadfence();
        __syncthreads();
        if (tid == 0) atomicAdd(&g_bar[1], 1u);  // matrix slice ready
    } else {
        // ============ blocks 64..127: zero the mask (overlapped with merge) ============
        float4* mz = (float4*)mask + (long long)(bid - 64) * 8192;
        float4 z = make_float4(0.f, 0.f, 0.f, 0.f);
        for (int i = tid; i < 8192; i += 1024) mz[i] = z;
        __threadfence();
        __syncthreads();
        if (tid == 0) atomicAdd(&g_bar[3], 1u);  // zero slice ready
    }

    // ============ Phase 2D: greedy NMS (8 blocks; sel still in smem) ============
    if (bid < 64 && (bid & 7) == 0) {
        int b = bid >> 3;
        wait_ge(1, (round + 1u) * 64u);  // all matrix slices ready

        // preload this batch's matrix into shared (S.K region is dead)
        unsigned* Msm = (unsigned*)S.K;
        for (int i = tid; i < 2048; i += 1024) Msm[i] = __ldcg(&g_M[b * 2048 + i]);
        __syncthreads();

        if (wrp == 0) {
            unsigned rem[8] = {0, 0, 0, 0, 0, 0, 0, 0};
            int kc = 0;
            bool done = false;
            unsigned lower = (1u << lane) - 1u;
            for (int c = 0; c < 8 && !done; ++c) {
                int i = c * 32 + lane;
                unsigned row[8];
#pragma unroll
                for (int w = 0; w < 8; ++w) row[w] = Msm[i * 8 + w];
                bool v = S.ssc[i] > 0.0f;
                bool psup = (rem[c] >> lane) & 1u;
                unsigned wchunk = row[c] & lower;

                bool k = v && !psup;
                unsigned km = __ballot_sync(0xffffffffu, k);
                for (int it = 0; it < 40; ++it) {
                    bool kn = v && !psup && ((wchunk & km) == 0u);
                    unsigned km2 = __ballot_sync(0xffffffffu, kn);
                    if (km2 == km) break;
                    km = km2;
                }
                k = (km >> lane) & 1u;

                if (km) {
                    int cnt = __popc(km);
                    int need = MAXI - kc;
                    int pos = __popc(km & lower);
                    if (k && pos < need) {
                        float* dr = det + (b * MAXI + kc + pos) * 6;
                        dr[0] = S.sy1[i]; dr[1] = S.sx1[i]; dr[2] = S.sy2[i]; dr[3] = S.sx2[i];
                        dr[4] = (float)S.scl[i]; dr[5] = S.ssc[i];
                    }
                    if (cnt >= need) {
                        kc = MAXI;
                        done = true;
                    } else {
#pragma unroll
                        for (int w = 0; w < 8; ++w)
                            rem[w] |= __reduce_or_sync(0xffffffffu, k ? row[w] : 0u);
                        kc += cnt;
                    }
                }
            }
            if (lane == 0) {
                S.s_kc = kc;
                S.s_fb = (kc < MAXI && S.nvalid > MSEL) ? 1 : 0;
            }
        }
        __syncthreads();

        // rare fallback: serial warp NMS over virtual 16-way merged stream
        if (S.s_fb && wrp == 0) {
            int kc = 0;
            int hp[16];
#pragma unroll
            for (int r = 0; r < 16; ++r) hp[r] = 0;
            for (int iter = 0; iter < NN && kc < MAXI; ++iter) {
                unsigned long long bk = 0;
                int br = -1;
#pragma unroll
                for (int r = 0; r < 16; ++r) {
                    if (hp[r] < 128) {
                        unsigned long long kk = __ldg(&g_key[b * 2048 + r * 128 + hp[r]]);
                        if (kk > bk) { bk = kk; br = r; }
                    }
                }
                if (bk == 0) break;
                hp[br]++;
                int idx = (int)(0xFFFFFFFFu - (unsigned)(bk & 0xFFFFFFFFull));
                int gi = b * NN + idx;
                float4 bx = g_box4[gi];
                float y1 = bx.x, x1 = bx.y, y2 = bx.z, x2 = bx.w;
                float cf = (float)g_cls[gi];
                float score = __uint_as_float((unsigned)(bk >> 32));
                float oy1 = y1 + 2.0f * cf, ox1 = x1 + 2.0f * cf;
                float oy2 = y2 + 2.0f * cf, ox2 = x2 + 2.0f * cf;
                float ar = (oy2 - oy1) * (ox2 - ox1);
                bool sup = false;
                for (int j = lane; j < kc; j += 32) {
                    float yy1 = fmaxf(oy1, S.ky1[j]);
                    float xx1 = fmaxf(ox1, S.kx1[j]);
                    float yy2 = fminf(oy2, S.ky2[j]);
                    float xx2 = fminf(ox2, S.kx2[j]);
                    float inter = fmaxf(yy2 - yy1, 0.0f) * fmaxf(xx2 - xx1, 0.0f);
                    float uni = ar + S.kar[j] - inter;
                    float iou = inter / fmaxf(uni, 1e-12f);
                    sup |= (iou > 0.3f);
                }
                if (!__any_sync(0xffffffffu, sup)) {
                    if (lane == 0) {
                        S.ky1[kc] = oy1; S.kx1[kc] = ox1; S.ky2[kc] = oy2; S.kx2[kc] = ox2;
                        S.kar[kc] = ar;
                        float* dr = det + (b * MAXI + kc) * 6;
                        dr[0] = y1; dr[1] = x1; dr[2] = y2; dr[3] = x2;
                        dr[4] = cf; dr[5] = score;
                    }
                    kc++;
                }
                __syncwarp();
            }
            if (lane == 0) S.s_kc = kc;
        }
        __syncthreads();

        int kc = S.s_kc;
        for (int t = tid; t < (MAXI - kc) * 6; t += 1024)
            det[(b * MAXI + kc) * 6 + t] = 0.0f;
        __threadfence();
        __syncthreads();
        if (tid == 0) atomicAdd(&g_bar[2], 1u);  // det[b] ready
    }

    // ============ wait for det + mask zeroing, then rect fill ============
    if (tid == 0) {
        unsigned td = (round + 1u) * 8u;
        unsigned tz = (round + 1u) * 64u;
        while (*(volatile unsigned*)&g_bar[2] < td) {}
        while (*(volatile unsigned*)&g_bar[3] < tz) {}
    }
    __syncthreads();

    for (int task = bid; task < BB * MAXI; task += GRID) {
        int b = task / MAXI;
        const float* dr = det + task * 6;
        float2 p01 = __ldcg((const float2*)dr);
        float2 p23 = __ldcg((const float2*)(dr + 2));
        float y1 = p01.x, x1 = p01.y, y2 = p23.x, x2 = p23.y;
        if (!(y2 > y1) || !(x2 > x1)) continue;  // empty / padded rows

        int hs = max(0, (int)floorf(512.0f * y1 - 0.5f));
        int he = min(HH - 1, (int)ceilf(512.0f * y2 - 0.5f));
        int ws = max(0, (int)floorf(512.0f * x1 - 0.5f));
        int we = min(WW - 1, (int)ceilf(512.0f * x2 - 0.5f));
        int rw = we - ws + 1;
        int npix = (he - hs + 1) * rw;
        float* mb = mask + (long long)b * HH * WW;
        for (int idx = tid; idx < npix; idx += 1024) {
            int h = hs + idx / rw;
            int x = ws + idx % rw;
            float ys = ((float)h + 0.5f) * (1.0f / 512.0f);
            float xs = ((float)x + 0.5f) * (1.0f / 512.0f);
            if (ys >= y1 && ys < y2 && xs >= x1 && xs < x2)
                mb[h * WW + x] = 1.0f;
        }
    }
}

// ---------------------------------------------------------------------------
extern "C" void kernel_launch(void* const* d_in, const int* in_sizes, int n_in,
                              void* d_out, int out_size) {
    const float* rois = (const float*)d_in[0];
    const float* probs = (const float*)d_in[1];
    const float* deltas = (const float*)d_in[2];
    const float* stdv = (const float*)d_in[3];
    float* det = (float*)d_out;                   // [B,100,6]
    float* mask = (float*)d_out + BB * MAXI * 6;  // [B,512,512]

    fused_all<<<GRID, 1024>>>(rois, probs, deltas, stdv, det, mask);
}